// round 12
// baseline (speedup 1.0000x reference)
#include <cuda_runtime.h>
#include <math.h>

#define D    128
#define HC   128
#define TD   32
#define MD   64
#define AD   96    // TD + MD
#define NMAX 50048
#define EMAX 500224
#define CHUNK 16   // sorted positions per warp

// scratch (static device memory — no allocations allowed)
__device__ float g_q[NMAX * HC];
__device__ float g_k[NMAX * HC];
__device__ float g_v[NMAX * HC];
__device__ float g_sk[NMAX * HC];
__device__ float g_mq[NMAX * 2 * AD];    // per-head We^T q  (= x@M + bm)
__device__ float g_accA[NMAX * 2 * AD];  // sum_e w_h * attr
__device__ float g_den[NMAX * 2];
__device__ int   g_cnt[NMAX];
__device__ int   g_cur[NMAX];
__device__ int4  g_es[EMAX];             // sorted (src, dst, time, eid)
__device__ int   g_bsum[64];
__device__ float g_M[D * 2 * AD];        // fused Wq@We^T per head  [k][192]
__device__ float g_bm[2 * AD];

typedef unsigned long long ull;

__device__ __forceinline__ ull pack2(float lo, float hi) {
    ull r; asm("mov.b64 %0, {%1, %2};" : "=l"(r) : "f"(lo), "f"(hi)); return r;
}
__device__ __forceinline__ void unpack2(ull v, float& lo, float& hi) {
    asm("mov.b64 {%0, %1}, %2;" : "=f"(lo), "=f"(hi) : "l"(v));
}
__device__ __forceinline__ ull ffma2(ull a, ull b, ull c) {
    ull d; asm("fma.rn.f32x2 %0, %1, %2, %3;" : "=l"(d) : "l"(a), "l"(b), "l"(c)); return d;
}
__device__ __forceinline__ void red_add_v4(float* addr, float4 v) {
    asm volatile("red.global.add.v4.f32 [%0], {%1,%2,%3,%4};"
                 :: "l"(addr), "f"(v.x), "f"(v.y), "f"(v.z), "f"(v.w) : "memory");
}

// ---------------------------------------------------------------------------
// K0: zero accA + cnt
// ---------------------------------------------------------------------------
__global__ void zero_kernel(int n) {
    int i = blockIdx.x * blockDim.x + threadIdx.x;
    if (i < n * 2 * AD) g_accA[i] = 0.0f;
    if (i < n)          g_cnt[i] = 0;
}

// ---------------------------------------------------------------------------
// KM: precompute M[k, h*96+j] = sum_{c<64} Wq[k,64h+c] * We[j,64h+c]
//     and bm[h*96+j]          = sum_{c<64} bq[64h+c]   * We[j,64h+c]
// grid (16, 2): 8 k-rows per block, head = blockIdx.y; 96 threads (j)
// ---------------------------------------------------------------------------
__global__ __launch_bounds__(96) void precM_kernel(
    const float* __restrict__ Wq, const float* __restrict__ bq,
    const float* __restrict__ We)
{
    __shared__ float We_s[96][65];
    __shared__ float Wq_s[8][65];
    const int h  = blockIdx.y;
    const int k0 = blockIdx.x * 8;
    const int j  = threadIdx.x;

    for (int i = j; i < 96 * 64; i += 96) {
        const int jj = i >> 6, c = i & 63;
        We_s[jj][c] = We[jj * HC + 64 * h + c];
    }
    for (int i = j; i < 8 * 64; i += 96) {
        const int kk = i >> 6, c = i & 63;
        Wq_s[kk][c] = Wq[(k0 + kk) * HC + 64 * h + c];
    }
    __syncthreads();

    float wj[64];
    #pragma unroll
    for (int c = 0; c < 64; c++) wj[c] = We_s[j][c];

    #pragma unroll
    for (int kk = 0; kk < 8; kk++) {
        float acc = 0.0f;
        #pragma unroll
        for (int c = 0; c < 64; c++) acc += Wq_s[kk][c] * wj[c];
        g_M[(k0 + kk) * (2 * AD) + h * AD + j] = acc;
    }
    if (blockIdx.x == 0) {
        float acc = 0.0f;
        #pragma unroll
        for (int c = 0; c < 64; c++) acc += bq[64 * h + c] * wj[c];
        g_bm[h * AD + j] = acc;
    }
}

// ---------------------------------------------------------------------------
// K1: fused node projections  q/k/v/skip/mq = x @ [W | M] + b   (+ zero out/den)
// Weights double-buffered through smem in 8-k tiles. mq columns: thread c
// owns M-col c (all warps) and M-col 128+c (warps 0-1, warp-uniform branch).
// ---------------------------------------------------------------------------
__global__ __launch_bounds__(128) void proj_kernel(
    const float* __restrict__ x,
    const float* __restrict__ Wq, const float* __restrict__ bq,
    const float* __restrict__ Wk, const float* __restrict__ bk,
    const float* __restrict__ Wv, const float* __restrict__ bv,
    const float* __restrict__ Ws, const float* __restrict__ bs,
    float* __restrict__ out, int n)
{
    __shared__ __align__(16) float2 xs2[D][9];
    __shared__ float Wt_s[2][8][4][HC];     // q/k/v/skip tiles
    __shared__ float Wm_s[2][8][2 * AD];    // M tiles
    const int r0 = blockIdx.x * 16;
    const int c  = threadIdx.x;

    #pragma unroll
    for (int r = 0; r < 16; r++) {
        const int row = r0 + r;
        if (row < n) {
            out[(size_t)row * HC + c] = 0.0f;
            if (c < 2) g_den[row * 2 + c] = 0.0f;
        }
    }
    #pragma unroll
    for (int r = 0; r < 16; r++) {
        const int row = r0 + r;
        const float v = (row < n) ? x[(size_t)row * D + c] : 0.0f;
        ((float*)&xs2[c][r >> 1])[r & 1] = v;
    }

    auto stage = [&](int t, int b) {
        const int k0 = t * 8;
        #pragma unroll
        for (int kk = 0; kk < 8; kk++) {
            Wt_s[b][kk][0][c] = Wq[(k0 + kk) * HC + c];
            Wt_s[b][kk][1][c] = Wk[(k0 + kk) * HC + c];
            Wt_s[b][kk][2][c] = Wv[(k0 + kk) * HC + c];
            Wt_s[b][kk][3][c] = Ws[(k0 + kk) * HC + c];
            Wm_s[b][kk][c] = g_M[(k0 + kk) * (2 * AD) + c];
            if (c < 64)
                Wm_s[b][kk][128 + c] = g_M[(k0 + kk) * (2 * AD) + 128 + c];
        }
    };

    stage(0, 0);
    __syncthreads();

    ull aq[8], ak[8], av[8], aw[8], am1[8], am2[8];
    #pragma unroll
    for (int r = 0; r < 8; r++) {
        aq[r] = 0; ak[r] = 0; av[r] = 0; aw[r] = 0; am1[r] = 0; am2[r] = 0;
    }

    for (int t = 0; t < 16; t++) {
        const int b = t & 1;
        if (t + 1 < 16) stage(t + 1, b ^ 1);
        #pragma unroll
        for (int kk = 0; kk < 8; kk++) {
            const int k = t * 8 + kk;
            const float wq = Wt_s[b][kk][0][c];
            const float wk = Wt_s[b][kk][1][c];
            const float wv = Wt_s[b][kk][2][c];
            const float ws = Wt_s[b][kk][3][c];
            const float wm = Wm_s[b][kk][c];
            const ull wq2 = pack2(wq, wq);
            const ull wk2 = pack2(wk, wk);
            const ull wv2 = pack2(wv, wv);
            const ull ws2 = pack2(ws, ws);
            const ull wm2 = pack2(wm, wm);
            #pragma unroll
            for (int r = 0; r < 8; r++) {
                const ull xv2 = *(const ull*)&xs2[k][r];
                aq[r]  = ffma2(xv2, wq2, aq[r]);
                ak[r]  = ffma2(xv2, wk2, ak[r]);
                av[r]  = ffma2(xv2, wv2, av[r]);
                aw[r]  = ffma2(xv2, ws2, aw[r]);
                am1[r] = ffma2(xv2, wm2, am1[r]);
            }
            if (c < 64) {   // warp-uniform: warps 0-1 only
                const float wmB = Wm_s[b][kk][128 + c];
                const ull wmB2 = pack2(wmB, wmB);
                #pragma unroll
                for (int r = 0; r < 8; r++) {
                    const ull xv2 = *(const ull*)&xs2[k][r];
                    am2[r] = ffma2(xv2, wmB2, am2[r]);
                }
            }
        }
        __syncthreads();
    }

    const float bqv = bq[c], bkv = bk[c], bvv = bv[c], bsv = bs[c];
    const float bm1 = g_bm[c];
    #pragma unroll
    for (int r = 0; r < 8; r++) {
        float lo, hi;
        const int rowL = r0 + 2 * r, rowH = rowL + 1;
        unpack2(aq[r], lo, hi);
        if (rowL < n) g_q[(size_t)rowL * HC + c] = lo + bqv;
        if (rowH < n) g_q[(size_t)rowH * HC + c] = hi + bqv;
        unpack2(ak[r], lo, hi);
        if (rowL < n) g_k[(size_t)rowL * HC + c] = lo + bkv;
        if (rowH < n) g_k[(size_t)rowH * HC + c] = hi + bkv;
        unpack2(av[r], lo, hi);
        if (rowL < n) g_v[(size_t)rowL * HC + c] = lo + bvv;
        if (rowH < n) g_v[(size_t)rowH * HC + c] = hi + bvv;
        unpack2(aw[r], lo, hi);
        if (rowL < n) g_sk[(size_t)rowL * HC + c] = lo + bsv;
        if (rowH < n) g_sk[(size_t)rowH * HC + c] = hi + bsv;
        unpack2(am1[r], lo, hi);
        if (rowL < n) g_mq[(size_t)rowL * (2 * AD) + c] = lo + bm1;
        if (rowH < n) g_mq[(size_t)rowH * (2 * AD) + c] = hi + bm1;
    }
    if (c < 64) {
        const float bm2 = g_bm[128 + c];
        #pragma unroll
        for (int r = 0; r < 8; r++) {
            float lo, hi;
            const int rowL = r0 + 2 * r, rowH = rowL + 1;
            unpack2(am2[r], lo, hi);
            if (rowL < n) g_mq[(size_t)rowL * (2 * AD) + 128 + c] = lo + bm2;
            if (rowH < n) g_mq[(size_t)rowH * (2 * AD) + 128 + c] = hi + bm2;
        }
    }
}

// ---------------------------------------------------------------------------
// K3: histogram of dst
// ---------------------------------------------------------------------------
__global__ void hist_kernel(const int* __restrict__ ei, int E) {
    int e = blockIdx.x * blockDim.x + threadIdx.x;
    if (e < E) atomicAdd(&g_cnt[ei[E + e]], 1);
}

// ---------------------------------------------------------------------------
// K4a: per-block sums of cnt
// ---------------------------------------------------------------------------
__global__ __launch_bounds__(1024) void scan_bsum_kernel(int n) {
    __shared__ int ws[32];
    const int i = blockIdx.x * 1024 + threadIdx.x;
    int v = (i < n) ? g_cnt[i] : 0;
    #pragma unroll
    for (int off = 16; off; off >>= 1) v += __shfl_xor_sync(~0u, v, off);
    if ((threadIdx.x & 31) == 0) ws[threadIdx.x >> 5] = v;
    __syncthreads();
    if (threadIdx.x < 32) {
        int s = ws[threadIdx.x];
        #pragma unroll
        for (int off = 16; off; off >>= 1) s += __shfl_xor_sync(~0u, s, off);
        if (threadIdx.x == 0) g_bsum[blockIdx.x] = s;
    }
}
// K4b: apply (each block sums preceding block sums itself)
__global__ __launch_bounds__(1024) void scan_apply_kernel(int n) {
    __shared__ int s[1024];
    const int tid = threadIdx.x;
    const int i = blockIdx.x * 1024 + tid;
    int base = 0;
    for (int b = 0; b < blockIdx.x; b++) base += g_bsum[b];
    const int v = (i < n) ? g_cnt[i] : 0;
    s[tid] = v;
    __syncthreads();
    #pragma unroll
    for (int off = 1; off < 1024; off <<= 1) {
        const int o = (tid >= off) ? s[tid - off] : 0;
        __syncthreads();
        s[tid] += o;
        __syncthreads();
    }
    if (i < n) g_cur[i] = base + s[tid] - v;
}

// ---------------------------------------------------------------------------
// K5: build sorted edge records (src, dst, time, eid)
// ---------------------------------------------------------------------------
__global__ void perm_kernel(const int* __restrict__ ei, const int* __restrict__ et, int E) {
    int e = blockIdx.x * blockDim.x + threadIdx.x;
    if (e < E) {
        const int s = ei[e], d = ei[E + e], t = et[e];
        const int pos = atomicAdd(&g_cur[d], 1);
        g_es[pos] = make_int4(s, d, t, e);
    }
}

// ---------------------------------------------------------------------------
// K6: edge kernel over dst-sorted records, 2 edges per iteration.
// ---------------------------------------------------------------------------
__global__ __launch_bounds__(256) void edge_kernel(
    const float* __restrict__ msg,  // [E,64]
    const float* __restrict__ Wt, const float* __restrict__ bt,
    float* __restrict__ out, int E)
{
    const int gw   = (blockIdx.x * blockDim.x + threadIdx.x) >> 5;
    const int lane = threadIdx.x & 31;
    int p = gw * CHUNK;
    if (p >= E) return;
    const int pend = min(p + CHUNK, E);

    const int  ll      = lane % 12;
    const bool is_a    = lane < 24;
    const bool a_head1 = (lane >= 12) && (lane < 24);
    const bool is_cos  = is_a && (ll < 4);

    float wt8[8], bt8[8];
    if (is_cos) {
        #pragma unroll
        for (int m = 0; m < 8; m++) { wt8[m] = Wt[8 * ll + m]; bt8[m] = bt[8 * ll + m]; }
    }

    int cur_dst = -1;
    float4 acc_v = make_float4(0, 0, 0, 0);
    float  accA[8] = {};
    float  den0 = 0.0f, den1 = 0.0f;

    auto flush = [&]() {
        if (cur_dst >= 0) {
            red_add_v4(out + (size_t)cur_dst * HC + 4 * lane, acc_v);
            if (is_a) {
                float* a = g_accA + (size_t)cur_dst * (2 * AD) + 8 * lane;
                red_add_v4(a,     make_float4(accA[0], accA[1], accA[2], accA[3]));
                red_add_v4(a + 4, make_float4(accA[4], accA[5], accA[6], accA[7]));
            }
            if (lane == 0)  atomicAdd(&g_den[cur_dst * 2],     den0);
            if (lane == 16) atomicAdd(&g_den[cur_dst * 2 + 1], den1);
            acc_v = make_float4(0, 0, 0, 0);
            #pragma unroll
            for (int m = 0; m < 8; m++) accA[m] = 0.0f;
            den0 = 0.0f; den1 = 0.0f;
        }
    };

    for (int pb = p; pb < pend; pb += 2) {
        const bool has1 = (pb + 1 < pend);
        const int4 m0 = g_es[pb];
        const int4 m1 = has1 ? g_es[pb + 1] : m0;
        const int s0 = m0.x, dA = m0.y, t0 = m0.z, e0 = m0.w;
        const int s1 = m1.x, dB = m1.y, t1 = m1.z, e1 = m1.w;

        // ---- issue all gathers up front (MLP) ----
        const float4 k40 = ((const float4*)(g_k + (size_t)s0 * HC))[lane];
        const float4 k41 = ((const float4*)(g_k + (size_t)s1 * HC))[lane];
        const float4 v40 = ((const float4*)(g_v + (size_t)s0 * HC))[lane];
        const float4 v41 = ((const float4*)(g_v + (size_t)s1 * HC))[lane];
        const float4 q40 = ((const float4*)(g_q + (size_t)dA * HC))[lane];
        const float4 q41 = ((const float4*)(g_q + (size_t)dB * HC))[lane];

        float mq0[8], mq1[8];
        if (is_a) {
            const float4 a0 = *(const float4*)(g_mq + (size_t)dA * (2 * AD) + 8 * lane);
            const float4 b0 = *(const float4*)(g_mq + (size_t)dA * (2 * AD) + 8 * lane + 4);
            const float4 a1 = *(const float4*)(g_mq + (size_t)dB * (2 * AD) + 8 * lane);
            const float4 b1 = *(const float4*)(g_mq + (size_t)dB * (2 * AD) + 8 * lane + 4);
            mq0[0]=a0.x; mq0[1]=a0.y; mq0[2]=a0.z; mq0[3]=a0.w;
            mq0[4]=b0.x; mq0[5]=b0.y; mq0[6]=b0.z; mq0[7]=b0.w;
            mq1[0]=a1.x; mq1[1]=a1.y; mq1[2]=a1.z; mq1[3]=a1.w;
            mq1[4]=b1.x; mq1[5]=b1.y; mq1[6]=b1.z; mq1[7]=b1.w;
        }

        // ---- attr slices ----
        float a80[8], a81[8];
        if (is_cos) {
            const float tf0 = (float)t0, tf1 = (float)t1;
            #pragma unroll
            for (int m = 0; m < 8; m++) {
                a80[m] = cosf(tf0 * wt8[m] + bt8[m]);
                a81[m] = cosf(tf1 * wt8[m] + bt8[m]);
            }
        } else if (is_a) {
            const float4 x00 = *(const float4*)(msg + (size_t)e0 * MD + 8 * (ll - 4));
            const float4 x01 = *(const float4*)(msg + (size_t)e0 * MD + 8 * (ll - 4) + 4);
            const float4 x10 = *(const float4*)(msg + (size_t)e1 * MD + 8 * (ll - 4));
            const float4 x11 = *(const float4*)(msg + (size_t)e1 * MD + 8 * (ll - 4) + 4);
            a80[0]=x00.x; a80[1]=x00.y; a80[2]=x00.z; a80[3]=x00.w;
            a80[4]=x01.x; a80[5]=x01.y; a80[6]=x01.z; a80[7]=x01.w;
            a81[0]=x10.x; a81[1]=x10.y; a81[2]=x10.z; a81[3]=x10.w;
            a81[4]=x11.x; a81[5]=x11.y; a81[6]=x11.z; a81[7]=x11.w;
        } else {
            #pragma unroll
            for (int m = 0; m < 8; m++) { a80[m] = 0.0f; a81[m] = 0.0f; }
        }

        // ---- alpha partials (4 interleaved reduce chains) ----
        const float qk0 = q40.x*k40.x + q40.y*k40.y + q40.z*k40.z + q40.w*k40.w;
        const float qk1 = q41.x*k41.x + q41.y*k41.y + q41.z*k41.z + q41.w*k41.w;
        float am0 = 0.0f, am1 = 0.0f;
        #pragma unroll
        for (int m = 0; m < 8; m++) { am0 += a80[m]*mq0[m]; am1 += a81[m]*mq1[m]; }

        float p00 = (lane < 16 ? qk0 : 0.0f) + ((is_a && !a_head1) ? am0 : 0.0f);
        float p01 = (lane >= 16 ? qk0 : 0.0f) + (a_head1 ? am0 : 0.0f);
        float p10 = (lane < 16 ? qk1 : 0.0f) + ((is_a && !a_head1) ? am1 : 0.0f);
        float p11 = (lane >= 16 ? qk1 : 0.0f) + (a_head1 ? am1 : 0.0f);
        #pragma unroll
        for (int off = 16; off; off >>= 1) {
            p00 += __shfl_xor_sync(~0u, p00, off);
            p01 += __shfl_xor_sync(~0u, p01, off);
            p10 += __shfl_xor_sync(~0u, p10, off);
            p11 += __shfl_xor_sync(~0u, p11, off);
        }
        const float w00 = __expf(0.125f * p00);
        const float w01 = __expf(0.125f * p01);
        const float w10 = __expf(0.125f * p10);
        const float w11 = __expf(0.125f * p11);

        // ---- accumulate edge 0 ----
        if (dA != cur_dst) { flush(); cur_dst = dA; }
        {
            const float wv = (lane < 16) ? w00 : w01;
            acc_v.x += wv * v40.x; acc_v.y += wv * v40.y;
            acc_v.z += wv * v40.z; acc_v.w += wv * v40.w;
            const float wa = a_head1 ? w01 : w00;
            #pragma unroll
            for (int m = 0; m < 8; m++) accA[m] += wa * a80[m];
            den0 += w00; den1 += w01;
        }
        // ---- accumulate edge 1 ----
        if (has1) {
            if (dB != cur_dst) { flush(); cur_dst = dB; }
            const float wv = (lane < 16) ? w10 : w11;
            acc_v.x += wv * v41.x; acc_v.y += wv * v41.y;
            acc_v.z += wv * v41.z; acc_v.w += wv * v41.w;
            const float wa = a_head1 ? w11 : w10;
            #pragma unroll
            for (int m = 0; m < 8; m++) accA[m] += wa * a81[m];
            den0 += w10; den1 += w11;
        }
    }
    flush();
}

// ---------------------------------------------------------------------------
// K7: out = (out_v + accA @ We_head) / den + skip   (8 rows per block)
// ---------------------------------------------------------------------------
__global__ __launch_bounds__(128) void final_kernel(
    const float* __restrict__ We, float* __restrict__ out, int n)
{
    __shared__ __align__(16) float aS[8][2 * AD];
    const int r0 = blockIdx.x * 8;
    const int c  = threadIdx.x;
    const int h  = c >> 6;

    for (int i = c; i < 8 * 2 * AD; i += 128) {
        const int r = i / (2 * AD), jj = i % (2 * AD), row = r0 + r;
        aS[r][jj] = (row < n) ? g_accA[(size_t)row * (2 * AD) + jj] : 0.0f;
    }
    __syncthreads();

    float acc[8] = {};
    #pragma unroll 4
    for (int j = 0; j < AD; j++) {
        const float wv = We[j * HC + c];
        #pragma unroll
        for (int r = 0; r < 8; r++) acc[r] += wv * aS[r][AD * h + j];
    }
    #pragma unroll
    for (int r = 0; r < 8; r++) {
        const int row = r0 + r;
        if (row < n) {
            const size_t o = (size_t)row * HC + c;
            const float den = g_den[row * 2 + h] + 1e-16f;
            out[o] = (out[o] + acc[r]) / den + g_sk[o];
        }
    }
}

// ---------------------------------------------------------------------------
extern "C" void kernel_launch(void* const* d_in, const int* in_sizes, int n_in,
                              void* d_out, int out_size)
{
    const float* x   = (const float*)d_in[0];
    const int*   ei  = (const int*)d_in[1];
    const int*   et  = (const int*)d_in[2];
    const float* msg = (const float*)d_in[3];
    const float* Wt  = (const float*)d_in[4];
    const float* bt  = (const float*)d_in[5];
    const float* Wq  = (const float*)d_in[6];
    const float* bq  = (const float*)d_in[7];
    const float* Wk  = (const float*)d_in[8];
    const float* bk  = (const float*)d_in[9];
    const float* Wv  = (const float*)d_in[10];
    const float* bv  = (const float*)d_in[11];
    const float* We  = (const float*)d_in[12];
    const float* Ws  = (const float*)d_in[13];
    const float* bs  = (const float*)d_in[14];
    float* out = (float*)d_out;

    const int N = in_sizes[0] / D;
    const int E = in_sizes[2];
    const int NB = (N + 1023) / 1024;

    zero_kernel<<<(N * 2 * AD + 255) / 256, 256>>>(N);           // 0
    hist_kernel<<<(E + 255) / 256, 256>>>(ei, E);                // 1
    scan_bsum_kernel<<<NB, 1024>>>(N);                           // 2
    scan_apply_kernel<<<NB, 1024>>>(N);                          // 3
    precM_kernel<<<dim3(16, 2), 96>>>(Wq, bq, We);               // 4
    proj_kernel<<<(N + 15) / 16, 128>>>(x, Wq, bq, Wk, bk,       // 5 <- ncu slot
                                        Wv, bv, Ws, bs, out, N);
    perm_kernel<<<(E + 255) / 256, 256>>>(ei, et, E);            // 6
    const int warps = (E + CHUNK - 1) / CHUNK;
    edge_kernel<<<(warps + 7) / 8, 256>>>(msg, Wt, bt, out, E);  // 7
    final_kernel<<<(N + 7) / 8, 128>>>(We, out, N);              // 8
}

// round 15
// speedup vs baseline: 1.0056x; 1.0056x over previous
#include <cuda_runtime.h>
#include <math.h>

#define D    128
#define HC   128
#define TD   32
#define MD   64
#define AD   96    // TD + MD
#define NMAX 50048
#define EMAX 500224
#define CHUNK 16   // sorted positions per warp

// scratch (static device memory — no allocations allowed)
__device__ float g_q[NMAX * HC];
__device__ float g_k[NMAX * HC];
__device__ float g_v[NMAX * HC];
__device__ float g_sk[NMAX * HC];
__device__ float g_mq[NMAX * 2 * AD];    // per-head We^T q
__device__ float g_accA[NMAX * 2 * AD];  // sum_e w_h * attr
__device__ float g_den[NMAX * 2];
__device__ int   g_cnt[NMAX];
__device__ int   g_cur[NMAX];
__device__ int4  g_es[EMAX];             // sorted (src, dst, time, eid)
__device__ int   g_bsum[64];

typedef unsigned long long ull;

__device__ __forceinline__ ull pack2(float lo, float hi) {
    ull r; asm("mov.b64 %0, {%1, %2};" : "=l"(r) : "f"(lo), "f"(hi)); return r;
}
__device__ __forceinline__ void unpack2(ull v, float& lo, float& hi) {
    asm("mov.b64 {%0, %1}, %2;" : "=f"(lo), "=f"(hi) : "l"(v));
}
__device__ __forceinline__ ull ffma2(ull a, ull b, ull c) {
    ull d; asm("fma.rn.f32x2 %0, %1, %2, %3;" : "=l"(d) : "l"(a), "l"(b), "l"(c)); return d;
}
__device__ __forceinline__ void red_add_v4(float* addr, float4 v) {
    asm volatile("red.global.add.v4.f32 [%0], {%1,%2,%3,%4};"
                 :: "l"(addr), "f"(v.x), "f"(v.y), "f"(v.z), "f"(v.w) : "memory");
}

// ---------------------------------------------------------------------------
// K0: zero accA + cnt
// ---------------------------------------------------------------------------
__global__ void zero_kernel(int n) {
    int i = blockIdx.x * blockDim.x + threadIdx.x;
    if (i < n * 2 * AD) g_accA[i] = 0.0f;
    if (i < n)          g_cnt[i] = 0;
}

// ---------------------------------------------------------------------------
// K1: fused node projections  q/k/v/skip = x @ W + b   (+ zero out/den)
// Weights double-buffered through smem in 8-k tiles (batched LDG prefetch).
// ---------------------------------------------------------------------------
__global__ __launch_bounds__(128) void proj_kernel(
    const float* __restrict__ x,
    const float* __restrict__ Wq, const float* __restrict__ bq,
    const float* __restrict__ Wk, const float* __restrict__ bk,
    const float* __restrict__ Wv, const float* __restrict__ bv,
    const float* __restrict__ Ws, const float* __restrict__ bs,
    float* __restrict__ out, int n)
{
    __shared__ __align__(16) float2 xs2[D][9];
    __shared__ float Wt_s[2][8][4][HC];   // [buf][kk][w][c]  2 x 16KB
    const int r0 = blockIdx.x * 16;
    const int c  = threadIdx.x;

    #pragma unroll
    for (int r = 0; r < 16; r++) {
        const int row = r0 + r;
        if (row < n) {
            out[(size_t)row * HC + c] = 0.0f;
            if (c < 2) g_den[row * 2 + c] = 0.0f;
        }
    }
    #pragma unroll
    for (int r = 0; r < 16; r++) {
        const int row = r0 + r;
        const float v = (row < n) ? x[(size_t)row * D + c] : 0.0f;
        ((float*)&xs2[c][r >> 1])[r & 1] = v;
    }

    auto stage = [&](int t, int b) {
        const int k0 = t * 8;
        #pragma unroll
        for (int kk = 0; kk < 8; kk++) {
            Wt_s[b][kk][0][c] = Wq[(k0 + kk) * HC + c];
            Wt_s[b][kk][1][c] = Wk[(k0 + kk) * HC + c];
            Wt_s[b][kk][2][c] = Wv[(k0 + kk) * HC + c];
            Wt_s[b][kk][3][c] = Ws[(k0 + kk) * HC + c];
        }
    };

    stage(0, 0);
    __syncthreads();

    ull aq[8], ak[8], av[8], aw[8];
    #pragma unroll
    for (int r = 0; r < 8; r++) { aq[r] = 0; ak[r] = 0; av[r] = 0; aw[r] = 0; }

    for (int t = 0; t < 16; t++) {
        const int b = t & 1;
        if (t + 1 < 16) stage(t + 1, b ^ 1);
        #pragma unroll
        for (int kk = 0; kk < 8; kk++) {
            const int k = t * 8 + kk;
            const float wq = Wt_s[b][kk][0][c];
            const float wk = Wt_s[b][kk][1][c];
            const float wv = Wt_s[b][kk][2][c];
            const float ws = Wt_s[b][kk][3][c];
            const ull wq2 = pack2(wq, wq);
            const ull wk2 = pack2(wk, wk);
            const ull wv2 = pack2(wv, wv);
            const ull ws2 = pack2(ws, ws);
            #pragma unroll
            for (int r = 0; r < 8; r++) {
                const ull xv2 = *(const ull*)&xs2[k][r];
                aq[r] = ffma2(xv2, wq2, aq[r]);
                ak[r] = ffma2(xv2, wk2, ak[r]);
                av[r] = ffma2(xv2, wv2, av[r]);
                aw[r] = ffma2(xv2, ws2, aw[r]);
            }
        }
        __syncthreads();
    }

    const float bqv = bq[c], bkv = bk[c], bvv = bv[c], bsv = bs[c];
    #pragma unroll
    for (int r = 0; r < 8; r++) {
        float lo, hi;
        const int rowL = r0 + 2 * r, rowH = rowL + 1;
        unpack2(aq[r], lo, hi);
        if (rowL < n) g_q[(size_t)rowL * HC + c] = lo + bqv;
        if (rowH < n) g_q[(size_t)rowH * HC + c] = hi + bqv;
        unpack2(ak[r], lo, hi);
        if (rowL < n) g_k[(size_t)rowL * HC + c] = lo + bkv;
        if (rowH < n) g_k[(size_t)rowH * HC + c] = hi + bkv;
        unpack2(av[r], lo, hi);
        if (rowL < n) g_v[(size_t)rowL * HC + c] = lo + bvv;
        if (rowH < n) g_v[(size_t)rowH * HC + c] = hi + bvv;
        unpack2(aw[r], lo, hi);
        if (rowL < n) g_sk[(size_t)rowL * HC + c] = lo + bsv;
        if (rowH < n) g_sk[(size_t)rowH * HC + c] = hi + bsv;
    }
}

// ---------------------------------------------------------------------------
// K3: histogram of dst
// ---------------------------------------------------------------------------
__global__ void hist_kernel(const int* __restrict__ ei, int E) {
    int e = blockIdx.x * blockDim.x + threadIdx.x;
    if (e < E) atomicAdd(&g_cnt[ei[E + e]], 1);
}

// ---------------------------------------------------------------------------
// K2: mq[n, h, j] = sum_{c<64} We[j, 64h+c] * q[n, 64h+c]
// ---------------------------------------------------------------------------
__global__ __launch_bounds__(192) void mq_kernel(const float* __restrict__ We, int n) {
    __shared__ float We_s[2][96][65];
    __shared__ __align__(16) float qs[32][128];
    const int r0  = blockIdx.x * 32;
    const int tid = threadIdx.x;
    const int h   = tid / 96, j = tid % 96;

    for (int i = tid; i < 96 * 128; i += 192) {
        const int jj = i >> 7, cc = i & 127;
        We_s[cc >> 6][jj][cc & 63] = We[jj * HC + cc];
    }
    for (int i = tid; i < 32 * 128; i += 192) {
        const int r = i >> 7, c = i & 127, row = r0 + r;
        qs[r][c] = (row < n) ? g_q[(size_t)row * HC + c] : 0.0f;
    }
    __syncthreads();

    ull wr2[32];
    #pragma unroll
    for (int i = 0; i < 32; i++)
        wr2[i] = pack2(We_s[h][j][2 * i], We_s[h][j][2 * i + 1]);

    #pragma unroll
    for (int pass = 0; pass < 2; pass++) {
        ull acc2[16];
        #pragma unroll
        for (int r = 0; r < 16; r++) acc2[r] = 0;
        #pragma unroll 2
        for (int i = 0; i < 16; i++) {
            const ull w2a = wr2[2 * i], w2b = wr2[2 * i + 1];
            #pragma unroll
            for (int r = 0; r < 16; r++) {
                const ulonglong2 q4 =
                    *(const ulonglong2*)&qs[pass * 16 + r][64 * h + 4 * i];
                acc2[r] = ffma2(q4.x, w2a, acc2[r]);
                acc2[r] = ffma2(q4.y, w2b, acc2[r]);
            }
        }
        #pragma unroll
        for (int r = 0; r < 16; r++) {
            float lo, hi; unpack2(acc2[r], lo, hi);
            const int row = r0 + pass * 16 + r;
            if (row < n) g_mq[(size_t)row * (2 * AD) + h * AD + j] = lo + hi;
        }
    }
}

// ---------------------------------------------------------------------------
// K4a: per-block sums of cnt
// ---------------------------------------------------------------------------
__global__ __launch_bounds__(1024) void scan_bsum_kernel(int n) {
    __shared__ int ws[32];
    const int i = blockIdx.x * 1024 + threadIdx.x;
    int v = (i < n) ? g_cnt[i] : 0;
    #pragma unroll
    for (int off = 16; off; off >>= 1) v += __shfl_xor_sync(~0u, v, off);
    if ((threadIdx.x & 31) == 0) ws[threadIdx.x >> 5] = v;
    __syncthreads();
    if (threadIdx.x < 32) {
        int s = ws[threadIdx.x];
        #pragma unroll
        for (int off = 16; off; off >>= 1) s += __shfl_xor_sync(~0u, s, off);
        if (threadIdx.x == 0) g_bsum[blockIdx.x] = s;
    }
}
// K4b: apply (each block sums preceding block sums itself)
__global__ __launch_bounds__(1024) void scan_apply_kernel(int n) {
    __shared__ int s[1024];
    const int tid = threadIdx.x;
    const int i = blockIdx.x * 1024 + tid;
    int base = 0;
    for (int b = 0; b < blockIdx.x; b++) base += g_bsum[b];
    const int v = (i < n) ? g_cnt[i] : 0;
    s[tid] = v;
    __syncthreads();
    #pragma unroll
    for (int off = 1; off < 1024; off <<= 1) {
        const int o = (tid >= off) ? s[tid - off] : 0;
        __syncthreads();
        s[tid] += o;
        __syncthreads();
    }
    if (i < n) g_cur[i] = base + s[tid] - v;
}

// ---------------------------------------------------------------------------
// K5: build sorted edge records (src, dst, time, eid)
// ---------------------------------------------------------------------------
__global__ void perm_kernel(const int* __restrict__ ei, const int* __restrict__ et, int E) {
    int e = blockIdx.x * blockDim.x + threadIdx.x;
    if (e < E) {
        const int s = ei[e], d = ei[E + e], t = et[e];
        const int pos = atomicAdd(&g_cur[d], 1);
        g_es[pos] = make_int4(s, d, t, e);
    }
}

// ---------------------------------------------------------------------------
// K6: edge kernel over dst-sorted records, 2 edges per iteration.
// Lane layout (16-lane half per head):
//   channels: lane covers c = 4*lane (channel head == lane>>4)
//   attr/mq:  hl = lane&15; hl<12 active; flat attr index = 8*hl
//   alpha: ONE fused width-16 butterfly per edge (qk + attr.mq together)
// ALL per-lane operands zero-initialized -> inactive lanes add exact 0.0
// (0 * stale-register garbage was the R13 NaN).
// Metadata (g_es) prefetched one iteration ahead.
// ---------------------------------------------------------------------------
__global__ __launch_bounds__(256) void edge_kernel(
    const float* __restrict__ msg,  // [E,64]
    const float* __restrict__ Wt, const float* __restrict__ bt,
    float* __restrict__ out, int E)
{
    const int gw   = (blockIdx.x * blockDim.x + threadIdx.x) >> 5;
    const int lane = threadIdx.x & 31;
    int p = gw * CHUNK;
    if (p >= E) return;
    const int pend = min(p + CHUNK, E);

    const int  head   = lane >> 4;
    const int  hl     = lane & 15;
    const bool is_a   = hl < 12;
    const bool is_cos = hl < 4;

    float wt8[8] = {}, bt8[8] = {};
    if (is_cos) {
        #pragma unroll
        for (int m = 0; m < 8; m++) { wt8[m] = Wt[8 * hl + m]; bt8[m] = bt[8 * hl + m]; }
    }

    int cur_dst = -1;
    float4 acc_v = make_float4(0, 0, 0, 0);
    float  accA[8] = {};
    float  den = 0.0f;

    auto flush = [&]() {
        if (cur_dst >= 0) {
            red_add_v4(out + (size_t)cur_dst * HC + 4 * lane, acc_v);
            if (is_a) {
                float* a = g_accA + (size_t)cur_dst * (2 * AD) + head * AD + 8 * hl;
                red_add_v4(a,     make_float4(accA[0], accA[1], accA[2], accA[3]));
                red_add_v4(a + 4, make_float4(accA[4], accA[5], accA[6], accA[7]));
            }
            if (hl == 0) atomicAdd(&g_den[cur_dst * 2 + head], den);
            acc_v = make_float4(0, 0, 0, 0);
            #pragma unroll
            for (int m = 0; m < 8; m++) accA[m] = 0.0f;
            den = 0.0f;
        }
    };

    // prefetch first metadata pair
    int4 mA = g_es[p];
    int4 mB = (p + 1 < pend) ? g_es[p + 1] : mA;

    for (int pb = p; pb < pend; pb += 2) {
        const bool has1 = (pb + 1 < pend);
        const int4 m0 = mA, m1 = mB;
        // prefetch next pair (overlaps this iteration's compute)
        if (pb + 2 < pend) {
            mA = g_es[pb + 2];
            mB = (pb + 3 < pend) ? g_es[pb + 3] : mA;
        }
        const int s0 = m0.x, dA = m0.y, t0 = m0.z, e0 = m0.w;
        const int s1 = m1.x, dB = m1.y, t1 = m1.z, e1 = m1.w;

        // ---- issue all gathers up front (MLP) ----
        const float4 k40 = ((const float4*)(g_k + (size_t)s0 * HC))[lane];
        const float4 k41 = ((const float4*)(g_k + (size_t)s1 * HC))[lane];
        const float4 v40 = ((const float4*)(g_v + (size_t)s0 * HC))[lane];
        const float4 v41 = ((const float4*)(g_v + (size_t)s1 * HC))[lane];
        const float4 q40 = ((const float4*)(g_q + (size_t)dA * HC))[lane];
        const float4 q41 = ((const float4*)(g_q + (size_t)dB * HC))[lane];

        float mq0[8] = {}, mq1[8] = {};   // zero-init: inactive lanes add 0.0
        if (is_a) {
            const size_t off = (size_t)head * AD + 8 * hl;
            const float4 a0 = *(const float4*)(g_mq + (size_t)dA * (2 * AD) + off);
            const float4 b0 = *(const float4*)(g_mq + (size_t)dA * (2 * AD) + off + 4);
            const float4 a1 = *(const float4*)(g_mq + (size_t)dB * (2 * AD) + off);
            const float4 b1 = *(const float4*)(g_mq + (size_t)dB * (2 * AD) + off + 4);
            mq0[0]=a0.x; mq0[1]=a0.y; mq0[2]=a0.z; mq0[3]=a0.w;
            mq0[4]=b0.x; mq0[5]=b0.y; mq0[6]=b0.z; mq0[7]=b0.w;
            mq1[0]=a1.x; mq1[1]=a1.y; mq1[2]=a1.z; mq1[3]=a1.w;
            mq1[4]=b1.x; mq1[5]=b1.y; mq1[6]=b1.z; mq1[7]=b1.w;
        }

        // ---- attr slices (zero-init; only active lanes overwrite) ----
        float a80[8] = {}, a81[8] = {};
        if (is_cos) {
            const float tf0 = (float)t0, tf1 = (float)t1;
            #pragma unroll
            for (int m = 0; m < 8; m++) {
                a80[m] = cosf(tf0 * wt8[m] + bt8[m]);
                a81[m] = cosf(tf1 * wt8[m] + bt8[m]);
            }
        } else if (is_a) {
            const float4 x00 = *(const float4*)(msg + (size_t)e0 * MD + 8 * (hl - 4));
            const float4 x01 = *(const float4*)(msg + (size_t)e0 * MD + 8 * (hl - 4) + 4);
            const float4 x10 = *(const float4*)(msg + (size_t)e1 * MD + 8 * (hl - 4));
            const float4 x11 = *(const float4*)(msg + (size_t)e1 * MD + 8 * (hl - 4) + 4);
            a80[0]=x00.x; a80[1]=x00.y; a80[2]=x00.z; a80[3]=x00.w;
            a80[4]=x01.x; a80[5]=x01.y; a80[6]=x01.z; a80[7]=x01.w;
            a81[0]=x10.x; a81[1]=x10.y; a81[2]=x10.z; a81[3]=x10.w;
            a81[4]=x11.x; a81[5]=x11.y; a81[6]=x11.z; a81[7]=x11.w;
        }

        // ---- fused alpha: p = q.k + attr.mq, width-16 butterfly ----
        float p0 = q40.x*k40.x + q40.y*k40.y + q40.z*k40.z + q40.w*k40.w;
        float p1 = q41.x*k41.x + q41.y*k41.y + q41.z*k41.z + q41.w*k41.w;
        #pragma unroll
        for (int m = 0; m < 8; m++) { p0 += a80[m]*mq0[m]; p1 += a81[m]*mq1[m]; }
        #pragma unroll
        for (int off = 8; off; off >>= 1) {
            p0 += __shfl_xor_sync(~0u, p0, off);
            p1 += __shfl_xor_sync(~0u, p1, off);
        }
        const float w0 = __expf(0.125f * p0);   // this half's head weight
        const float w1 = __expf(0.125f * p1);

        // ---- accumulate edge 0 ----
        if (dA != cur_dst) { flush(); cur_dst = dA; }
        acc_v.x += w0 * v40.x; acc_v.y += w0 * v40.y;
        acc_v.z += w0 * v40.z; acc_v.w += w0 * v40.w;
        #pragma unroll
        for (int m = 0; m < 8; m++) accA[m] += w0 * a80[m];
        den += w0;
        // ---- accumulate edge 1 ----
        if (has1) {
            if (dB != cur_dst) { flush(); cur_dst = dB; }
            acc_v.x += w1 * v41.x; acc_v.y += w1 * v41.y;
            acc_v.z += w1 * v41.z; acc_v.w += w1 * v41.w;
            #pragma unroll
            for (int m = 0; m < 8; m++) accA[m] += w1 * a81[m];
            den += w1;
        }
    }
    flush();
}

// ---------------------------------------------------------------------------
// K7: out = (out_v + accA @ We_head) / den + skip   (8 rows per block)
// ---------------------------------------------------------------------------
__global__ __launch_bounds__(128) void final_kernel(
    const float* __restrict__ We, float* __restrict__ out, int n)
{
    __shared__ __align__(16) float aS[8][2 * AD];
    const int r0 = blockIdx.x * 8;
    const int c  = threadIdx.x;
    const int h  = c >> 6;

    for (int i = c; i < 8 * 2 * AD; i += 128) {
        const int r = i / (2 * AD), jj = i % (2 * AD), row = r0 + r;
        aS[r][jj] = (row < n) ? g_accA[(size_t)row * (2 * AD) + jj] : 0.0f;
    }
    __syncthreads();

    float acc[8] = {};
    #pragma unroll 4
    for (int j = 0; j < AD; j++) {
        const float wv = We[j * HC + c];
        #pragma unroll
        for (int r = 0; r < 8; r++) acc[r] += wv * aS[r][AD * h + j];
    }
    #pragma unroll
    for (int r = 0; r < 8; r++) {
        const int row = r0 + r;
        if (row < n) {
            const size_t o = (size_t)row * HC + c;
            const float den = g_den[row * 2 + h] + 1e-16f;
            out[o] = (out[o] + acc[r]) / den + g_sk[o];
        }
    }
}

// ---------------------------------------------------------------------------
extern "C" void kernel_launch(void* const* d_in, const int* in_sizes, int n_in,
                              void* d_out, int out_size)
{
    const float* x   = (const float*)d_in[0];
    const int*   ei  = (const int*)d_in[1];
    const int*   et  = (const int*)d_in[2];
    const float* msg = (const float*)d_in[3];
    const float* Wt  = (const float*)d_in[4];
    const float* bt  = (const float*)d_in[5];
    const float* Wq  = (const float*)d_in[6];
    const float* bq  = (const float*)d_in[7];
    const float* Wk  = (const float*)d_in[8];
    const float* bk  = (const float*)d_in[9];
    const float* Wv  = (const float*)d_in[10];
    const float* bv  = (const float*)d_in[11];
    const float* We  = (const float*)d_in[12];
    const float* Ws  = (const float*)d_in[13];
    const float* bs  = (const float*)d_in[14];
    float* out = (float*)d_out;

    const int N = in_sizes[0] / D;
    const int E = in_sizes[2];
    const int NB = (N + 1023) / 1024;

    zero_kernel<<<(N * 2 * AD + 255) / 256, 256>>>(N);           // 0
    hist_kernel<<<(E + 255) / 256, 256>>>(ei, E);                // 1
    scan_bsum_kernel<<<NB, 1024>>>(N);                           // 2
    proj_kernel<<<(N + 15) / 16, 128>>>(x, Wq, bq, Wk, bk,       // 3 <- capture slot
                                        Wv, bv, Ws, bs, out, N);
    mq_kernel<<<(N + 31) / 32, 192>>>(We, N);                    // 4
    scan_apply_kernel<<<NB, 1024>>>(N);                          // 5
    perm_kernel<<<(E + 255) / 256, 256>>>(ei, et, E);            // 6
    const int warps = (E + CHUNK - 1) / CHUNK;
    edge_kernel<<<(warps + 7) / 8, 256>>>(msg, Wt, bt, out, E);  // 7
    final_kernel<<<(N + 7) / 8, 128>>>(We, out, N);              // 8
}

// round 16
// speedup vs baseline: 1.0645x; 1.0585x over previous
#include <cuda_runtime.h>
#include <math.h>

#define D    128
#define HC   128
#define TD   32
#define MD   64
#define AD   96    // TD + MD
#define NMAX 50048
#define EMAX 500224
#define CHUNK 16   // sorted positions per warp

// scratch (static device memory — no allocations allowed)
__device__ float g_q[NMAX * HC];
__device__ float g_k[NMAX * HC];
__device__ float g_v[NMAX * HC];
__device__ float g_sk[NMAX * HC];
__device__ float g_mq[NMAX * 2 * AD];    // per-head We^T q
__device__ float g_accA[NMAX * 2 * AD];  // sum_e w_h * attr
__device__ float g_den[NMAX * 2];
__device__ int   g_cnt[NMAX];
__device__ int   g_cur[NMAX];
__device__ int4  g_es[EMAX];             // sorted (src, dst, time, eid)
__device__ int   g_bsum[64];

typedef unsigned long long ull;

__device__ __forceinline__ ull pack2(float lo, float hi) {
    ull r; asm("mov.b64 %0, {%1, %2};" : "=l"(r) : "f"(lo), "f"(hi)); return r;
}
__device__ __forceinline__ void unpack2(ull v, float& lo, float& hi) {
    asm("mov.b64 {%0, %1}, %2;" : "=f"(lo), "=f"(hi) : "l"(v));
}
__device__ __forceinline__ ull ffma2(ull a, ull b, ull c) {
    ull d; asm("fma.rn.f32x2 %0, %1, %2, %3;" : "=l"(d) : "l"(a), "l"(b), "l"(c)); return d;
}
__device__ __forceinline__ void red_add_v4(float* addr, float4 v) {
    asm volatile("red.global.add.v4.f32 [%0], {%1,%2,%3,%4};"
                 :: "l"(addr), "f"(v.x), "f"(v.y), "f"(v.z), "f"(v.w) : "memory");
}

// ---------------------------------------------------------------------------
// K0: zero accA + cnt
// ---------------------------------------------------------------------------
__global__ void zero_kernel(int n) {
    int i = blockIdx.x * blockDim.x + threadIdx.x;
    if (i < n * 2 * AD) g_accA[i] = 0.0f;
    if (i < n)          g_cnt[i] = 0;
}

// ---------------------------------------------------------------------------
// K1: fused node projections  q/k/v/skip = x @ W + b   (+ zero out/den)
// Weights staged as float4 {wq,wk,wv,ws} per column -> 1 LDS.128 per kk;
// x broadcasts read as LDS.128 (2 row-pairs per load). 5 LDS per kk vs 12.
// ---------------------------------------------------------------------------
__global__ __launch_bounds__(128) void proj_kernel(
    const float* __restrict__ x,
    const float* __restrict__ Wq, const float* __restrict__ bq,
    const float* __restrict__ Wk, const float* __restrict__ bk,
    const float* __restrict__ Wv, const float* __restrict__ bv,
    const float* __restrict__ Ws, const float* __restrict__ bs,
    float* __restrict__ out, int n)
{
    __shared__ __align__(16) float2 xs2[D][10];     // pad 10 -> 16B-aligned rows
    __shared__ __align__(16) float4 W4_s[2][8][HC]; // [buf][kk][c] = {q,k,v,s}
    const int r0 = blockIdx.x * 16;
    const int c  = threadIdx.x;

    #pragma unroll
    for (int r = 0; r < 16; r++) {
        const int row = r0 + r;
        if (row < n) {
            out[(size_t)row * HC + c] = 0.0f;
            if (c < 2) g_den[row * 2 + c] = 0.0f;
        }
    }
    #pragma unroll
    for (int r = 0; r < 16; r++) {
        const int row = r0 + r;
        const float v = (row < n) ? x[(size_t)row * D + c] : 0.0f;
        ((float*)&xs2[c][r >> 1])[r & 1] = v;
    }

    auto stage = [&](int t, int b) {
        const int k0 = t * 8;
        #pragma unroll
        for (int kk = 0; kk < 8; kk++) {
            W4_s[b][kk][c] = make_float4(Wq[(k0 + kk) * HC + c],
                                         Wk[(k0 + kk) * HC + c],
                                         Wv[(k0 + kk) * HC + c],
                                         Ws[(k0 + kk) * HC + c]);
        }
    };

    stage(0, 0);
    __syncthreads();

    ull aq[8], ak[8], av[8], aw[8];
    #pragma unroll
    for (int r = 0; r < 8; r++) { aq[r] = 0; ak[r] = 0; av[r] = 0; aw[r] = 0; }

    for (int t = 0; t < 16; t++) {
        const int b = t & 1;
        if (t + 1 < 16) stage(t + 1, b ^ 1);
        #pragma unroll
        for (int kk = 0; kk < 8; kk++) {
            const int k = t * 8 + kk;
            const float4 w4 = W4_s[b][kk][c];        // LDS.128
            const ull wq2 = pack2(w4.x, w4.x);
            const ull wk2 = pack2(w4.y, w4.y);
            const ull wv2 = pack2(w4.z, w4.z);
            const ull ws2 = pack2(w4.w, w4.w);
            #pragma unroll
            for (int rr = 0; rr < 4; rr++) {
                const ulonglong2 xv = *(const ulonglong2*)&xs2[k][2 * rr]; // LDS.128 bcast
                aq[2 * rr]     = ffma2(xv.x, wq2, aq[2 * rr]);
                aq[2 * rr + 1] = ffma2(xv.y, wq2, aq[2 * rr + 1]);
                ak[2 * rr]     = ffma2(xv.x, wk2, ak[2 * rr]);
                ak[2 * rr + 1] = ffma2(xv.y, wk2, ak[2 * rr + 1]);
                av[2 * rr]     = ffma2(xv.x, wv2, av[2 * rr]);
                av[2 * rr + 1] = ffma2(xv.y, wv2, av[2 * rr + 1]);
                aw[2 * rr]     = ffma2(xv.x, ws2, aw[2 * rr]);
                aw[2 * rr + 1] = ffma2(xv.y, ws2, aw[2 * rr + 1]);
            }
        }
        __syncthreads();
    }

    const float bqv = bq[c], bkv = bk[c], bvv = bv[c], bsv = bs[c];
    #pragma unroll
    for (int r = 0; r < 8; r++) {
        float lo, hi;
        const int rowL = r0 + 2 * r, rowH = rowL + 1;
        unpack2(aq[r], lo, hi);
        if (rowL < n) g_q[(size_t)rowL * HC + c] = lo + bqv;
        if (rowH < n) g_q[(size_t)rowH * HC + c] = hi + bqv;
        unpack2(ak[r], lo, hi);
        if (rowL < n) g_k[(size_t)rowL * HC + c] = lo + bkv;
        if (rowH < n) g_k[(size_t)rowH * HC + c] = hi + bkv;
        unpack2(av[r], lo, hi);
        if (rowL < n) g_v[(size_t)rowL * HC + c] = lo + bvv;
        if (rowH < n) g_v[(size_t)rowH * HC + c] = hi + bvv;
        unpack2(aw[r], lo, hi);
        if (rowL < n) g_sk[(size_t)rowL * HC + c] = lo + bsv;
        if (rowH < n) g_sk[(size_t)rowH * HC + c] = hi + bsv;
    }
}

// ---------------------------------------------------------------------------
// K3: histogram of dst
// ---------------------------------------------------------------------------
__global__ void hist_kernel(const int* __restrict__ ei, int E) {
    int e = blockIdx.x * blockDim.x + threadIdx.x;
    if (e < E) atomicAdd(&g_cnt[ei[E + e]], 1);
}

// ---------------------------------------------------------------------------
// K2: mq[n, h, j] = sum_{c<64} We[j, 64h+c] * q[n, 64h+c]
// ---------------------------------------------------------------------------
__global__ __launch_bounds__(192) void mq_kernel(const float* __restrict__ We, int n) {
    __shared__ float We_s[2][96][65];
    __shared__ __align__(16) float qs[32][128];
    const int r0  = blockIdx.x * 32;
    const int tid = threadIdx.x;
    const int h   = tid / 96, j = tid % 96;

    for (int i = tid; i < 96 * 128; i += 192) {
        const int jj = i >> 7, cc = i & 127;
        We_s[cc >> 6][jj][cc & 63] = We[jj * HC + cc];
    }
    for (int i = tid; i < 32 * 128; i += 192) {
        const int r = i >> 7, c = i & 127, row = r0 + r;
        qs[r][c] = (row < n) ? g_q[(size_t)row * HC + c] : 0.0f;
    }
    __syncthreads();

    ull wr2[32];
    #pragma unroll
    for (int i = 0; i < 32; i++)
        wr2[i] = pack2(We_s[h][j][2 * i], We_s[h][j][2 * i + 1]);

    #pragma unroll
    for (int pass = 0; pass < 2; pass++) {
        ull acc2[16];
        #pragma unroll
        for (int r = 0; r < 16; r++) acc2[r] = 0;
        #pragma unroll 2
        for (int i = 0; i < 16; i++) {
            const ull w2a = wr2[2 * i], w2b = wr2[2 * i + 1];
            #pragma unroll
            for (int r = 0; r < 16; r++) {
                const ulonglong2 q4 =
                    *(const ulonglong2*)&qs[pass * 16 + r][64 * h + 4 * i];
                acc2[r] = ffma2(q4.x, w2a, acc2[r]);
                acc2[r] = ffma2(q4.y, w2b, acc2[r]);
            }
        }
        #pragma unroll
        for (int r = 0; r < 16; r++) {
            float lo, hi; unpack2(acc2[r], lo, hi);
            const int row = r0 + pass * 16 + r;
            if (row < n) g_mq[(size_t)row * (2 * AD) + h * AD + j] = lo + hi;
        }
    }
}

// ---------------------------------------------------------------------------
// K4a: per-block sums of cnt
// ---------------------------------------------------------------------------
__global__ __launch_bounds__(1024) void scan_bsum_kernel(int n) {
    __shared__ int ws[32];
    const int i = blockIdx.x * 1024 + threadIdx.x;
    int v = (i < n) ? g_cnt[i] : 0;
    #pragma unroll
    for (int off = 16; off; off >>= 1) v += __shfl_xor_sync(~0u, v, off);
    if ((threadIdx.x & 31) == 0) ws[threadIdx.x >> 5] = v;
    __syncthreads();
    if (threadIdx.x < 32) {
        int s = ws[threadIdx.x];
        #pragma unroll
        for (int off = 16; off; off >>= 1) s += __shfl_xor_sync(~0u, s, off);
        if (threadIdx.x == 0) g_bsum[blockIdx.x] = s;
    }
}
// K4b: apply (each block sums preceding block sums itself)
__global__ __launch_bounds__(1024) void scan_apply_kernel(int n) {
    __shared__ int s[1024];
    const int tid = threadIdx.x;
    const int i = blockIdx.x * 1024 + tid;
    int base = 0;
    for (int b = 0; b < blockIdx.x; b++) base += g_bsum[b];
    const int v = (i < n) ? g_cnt[i] : 0;
    s[tid] = v;
    __syncthreads();
    #pragma unroll
    for (int off = 1; off < 1024; off <<= 1) {
        const int o = (tid >= off) ? s[tid - off] : 0;
        __syncthreads();
        s[tid] += o;
        __syncthreads();
    }
    if (i < n) g_cur[i] = base + s[tid] - v;
}

// ---------------------------------------------------------------------------
// K5: build sorted edge records (src, dst, time, eid)
// ---------------------------------------------------------------------------
__global__ void perm_kernel(const int* __restrict__ ei, const int* __restrict__ et, int E) {
    int e = blockIdx.x * blockDim.x + threadIdx.x;
    if (e < E) {
        const int s = ei[e], d = ei[E + e], t = et[e];
        const int pos = atomicAdd(&g_cur[d], 1);
        g_es[pos] = make_int4(s, d, t, e);
    }
}

// ---------------------------------------------------------------------------
// K6: edge kernel over dst-sorted records, 2 edges per iteration (R11 layout).
// ---------------------------------------------------------------------------
__global__ __launch_bounds__(256) void edge_kernel(
    const float* __restrict__ msg,  // [E,64]
    const float* __restrict__ Wt, const float* __restrict__ bt,
    float* __restrict__ out, int E)
{
    const int gw   = (blockIdx.x * blockDim.x + threadIdx.x) >> 5;
    const int lane = threadIdx.x & 31;
    int p = gw * CHUNK;
    if (p >= E) return;
    const int pend = min(p + CHUNK, E);

    const int  ll      = lane % 12;
    const bool is_a    = lane < 24;
    const bool a_head1 = (lane >= 12) && (lane < 24);
    const bool is_cos  = is_a && (ll < 4);

    float wt8[8], bt8[8];
    if (is_cos) {
        #pragma unroll
        for (int m = 0; m < 8; m++) { wt8[m] = Wt[8 * ll + m]; bt8[m] = bt[8 * ll + m]; }
    }

    int cur_dst = -1;
    float4 acc_v = make_float4(0, 0, 0, 0);
    float  accA[8] = {};
    float  den0 = 0.0f, den1 = 0.0f;

    auto flush = [&]() {
        if (cur_dst >= 0) {
            red_add_v4(out + (size_t)cur_dst * HC + 4 * lane, acc_v);
            if (is_a) {
                float* a = g_accA + (size_t)cur_dst * (2 * AD) + 8 * lane;
                red_add_v4(a,     make_float4(accA[0], accA[1], accA[2], accA[3]));
                red_add_v4(a + 4, make_float4(accA[4], accA[5], accA[6], accA[7]));
            }
            if (lane == 0)  atomicAdd(&g_den[cur_dst * 2],     den0);
            if (lane == 16) atomicAdd(&g_den[cur_dst * 2 + 1], den1);
            acc_v = make_float4(0, 0, 0, 0);
            #pragma unroll
            for (int m = 0; m < 8; m++) accA[m] = 0.0f;
            den0 = 0.0f; den1 = 0.0f;
        }
    };

    for (int pb = p; pb < pend; pb += 2) {
        const bool has1 = (pb + 1 < pend);
        const int4 m0 = g_es[pb];
        const int4 m1 = has1 ? g_es[pb + 1] : m0;
        const int s0 = m0.x, dA = m0.y, t0 = m0.z, e0 = m0.w;
        const int s1 = m1.x, dB = m1.y, t1 = m1.z, e1 = m1.w;

        // ---- issue all gathers up front (MLP) ----
        const float4 k40 = ((const float4*)(g_k + (size_t)s0 * HC))[lane];
        const float4 k41 = ((const float4*)(g_k + (size_t)s1 * HC))[lane];
        const float4 v40 = ((const float4*)(g_v + (size_t)s0 * HC))[lane];
        const float4 v41 = ((const float4*)(g_v + (size_t)s1 * HC))[lane];
        const float4 q40 = ((const float4*)(g_q + (size_t)dA * HC))[lane];
        const float4 q41 = ((const float4*)(g_q + (size_t)dB * HC))[lane];

        float mq0[8] = {}, mq1[8] = {};
        if (is_a) {
            const float4 a0 = *(const float4*)(g_mq + (size_t)dA * (2 * AD) + 8 * lane);
            const float4 b0 = *(const float4*)(g_mq + (size_t)dA * (2 * AD) + 8 * lane + 4);
            const float4 a1 = *(const float4*)(g_mq + (size_t)dB * (2 * AD) + 8 * lane);
            const float4 b1 = *(const float4*)(g_mq + (size_t)dB * (2 * AD) + 8 * lane + 4);
            mq0[0]=a0.x; mq0[1]=a0.y; mq0[2]=a0.z; mq0[3]=a0.w;
            mq0[4]=b0.x; mq0[5]=b0.y; mq0[6]=b0.z; mq0[7]=b0.w;
            mq1[0]=a1.x; mq1[1]=a1.y; mq1[2]=a1.z; mq1[3]=a1.w;
            mq1[4]=b1.x; mq1[5]=b1.y; mq1[6]=b1.z; mq1[7]=b1.w;
        }

        // ---- attr slices ----
        float a80[8] = {}, a81[8] = {};
        if (is_cos) {
            const float tf0 = (float)t0, tf1 = (float)t1;
            #pragma unroll
            for (int m = 0; m < 8; m++) {
                a80[m] = cosf(tf0 * wt8[m] + bt8[m]);
                a81[m] = cosf(tf1 * wt8[m] + bt8[m]);
            }
        } else if (is_a) {
            const float4 x00 = *(const float4*)(msg + (size_t)e0 * MD + 8 * (ll - 4));
            const float4 x01 = *(const float4*)(msg + (size_t)e0 * MD + 8 * (ll - 4) + 4);
            const float4 x10 = *(const float4*)(msg + (size_t)e1 * MD + 8 * (ll - 4));
            const float4 x11 = *(const float4*)(msg + (size_t)e1 * MD + 8 * (ll - 4) + 4);
            a80[0]=x00.x; a80[1]=x00.y; a80[2]=x00.z; a80[3]=x00.w;
            a80[4]=x01.x; a80[5]=x01.y; a80[6]=x01.z; a80[7]=x01.w;
            a81[0]=x10.x; a81[1]=x10.y; a81[2]=x10.z; a81[3]=x10.w;
            a81[4]=x11.x; a81[5]=x11.y; a81[6]=x11.z; a81[7]=x11.w;
        }

        // ---- alpha partials (4 interleaved reduce chains) ----
        const float qk0 = q40.x*k40.x + q40.y*k40.y + q40.z*k40.z + q40.w*k40.w;
        const float qk1 = q41.x*k41.x + q41.y*k41.y + q41.z*k41.z + q41.w*k41.w;
        float am0 = 0.0f, am1 = 0.0f;
        #pragma unroll
        for (int m = 0; m < 8; m++) { am0 += a80[m]*mq0[m]; am1 += a81[m]*mq1[m]; }

        float p00 = (lane < 16 ? qk0 : 0.0f) + ((is_a && !a_head1) ? am0 : 0.0f);
        float p01 = (lane >= 16 ? qk0 : 0.0f) + (a_head1 ? am0 : 0.0f);
        float p10 = (lane < 16 ? qk1 : 0.0f) + ((is_a && !a_head1) ? am1 : 0.0f);
        float p11 = (lane >= 16 ? qk1 : 0.0f) + (a_head1 ? am1 : 0.0f);
        #pragma unroll
        for (int off = 16; off; off >>= 1) {
            p00 += __shfl_xor_sync(~0u, p00, off);
            p01 += __shfl_xor_sync(~0u, p01, off);
            p10 += __shfl_xor_sync(~0u, p10, off);
            p11 += __shfl_xor_sync(~0u, p11, off);
        }
        const float w00 = __expf(0.125f * p00);
        const float w01 = __expf(0.125f * p01);
        const float w10 = __expf(0.125f * p10);
        const float w11 = __expf(0.125f * p11);

        // ---- accumulate edge 0 ----
        if (dA != cur_dst) { flush(); cur_dst = dA; }
        {
            const float wv = (lane < 16) ? w00 : w01;
            acc_v.x += wv * v40.x; acc_v.y += wv * v40.y;
            acc_v.z += wv * v40.z; acc_v.w += wv * v40.w;
            const float wa = a_head1 ? w01 : w00;
            #pragma unroll
            for (int m = 0; m < 8; m++) accA[m] += wa * a80[m];
            den0 += w00; den1 += w01;
        }
        // ---- accumulate edge 1 ----
        if (has1) {
            if (dB != cur_dst) { flush(); cur_dst = dB; }
            const float wv = (lane < 16) ? w10 : w11;
            acc_v.x += wv * v41.x; acc_v.y += wv * v41.y;
            acc_v.z += wv * v41.z; acc_v.w += wv * v41.w;
            const float wa = a_head1 ? w11 : w10;
            #pragma unroll
            for (int m = 0; m < 8; m++) accA[m] += wa * a81[m];
            den0 += w10; den1 += w11;
        }
    }
    flush();
}

// ---------------------------------------------------------------------------
// K7: out = (out_v + accA @ We_head) / den + skip   (8 rows per block)
// ---------------------------------------------------------------------------
__global__ __launch_bounds__(128) void final_kernel(
    const float* __restrict__ We, float* __restrict__ out, int n)
{
    __shared__ __align__(16) float aS[8][2 * AD];
    const int r0 = blockIdx.x * 8;
    const int c  = threadIdx.x;
    const int h  = c >> 6;

    for (int i = c; i < 8 * 2 * AD; i += 128) {
        const int r = i / (2 * AD), jj = i % (2 * AD), row = r0 + r;
        aS[r][jj] = (row < n) ? g_accA[(size_t)row * (2 * AD) + jj] : 0.0f;
    }
    __syncthreads();

    float acc[8] = {};
    #pragma unroll 4
    for (int j = 0; j < AD; j++) {
        const float wv = We[j * HC + c];
        #pragma unroll
        for (int r = 0; r < 8; r++) acc[r] += wv * aS[r][AD * h + j];
    }
    #pragma unroll
    for (int r = 0; r < 8; r++) {
        const int row = r0 + r;
        if (row < n) {
            const size_t o = (size_t)row * HC + c;
            const float den = g_den[row * 2 + h] + 1e-16f;
            out[o] = (out[o] + acc[r]) / den + g_sk[o];
        }
    }
}

// ---------------------------------------------------------------------------
extern "C" void kernel_launch(void* const* d_in, const int* in_sizes, int n_in,
                              void* d_out, int out_size)
{
    const float* x   = (const float*)d_in[0];
    const int*   ei  = (const int*)d_in[1];
    const int*   et  = (const int*)d_in[2];
    const float* msg = (const float*)d_in[3];
    const float* Wt  = (const float*)d_in[4];
    const float* bt  = (const float*)d_in[5];
    const float* Wq  = (const float*)d_in[6];
    const float* bq  = (const float*)d_in[7];
    const float* Wk  = (const float*)d_in[8];
    const float* bk  = (const float*)d_in[9];
    const float* Wv  = (const float*)d_in[10];
    const float* bv  = (const float*)d_in[11];
    const float* We  = (const float*)d_in[12];
    const float* Ws  = (const float*)d_in[13];
    const float* bs  = (const float*)d_in[14];
    float* out = (float*)d_out;

    const int N = in_sizes[0] / D;
    const int E = in_sizes[2];
    const int NB = (N + 1023) / 1024;

    zero_kernel<<<(N * 2 * AD + 255) / 256, 256>>>(N);           // 0
    hist_kernel<<<(E + 255) / 256, 256>>>(ei, E);                // 1
    scan_bsum_kernel<<<NB, 1024>>>(N);                           // 2
    proj_kernel<<<(N + 15) / 16, 128>>>(x, Wq, bq, Wk, bk,       // 3 <- capture slot
                                        Wv, bv, Ws, bs, out, N);
    mq_kernel<<<(N + 31) / 32, 192>>>(We, N);                    // 4
    scan_apply_kernel<<<NB, 1024>>>(N);                          // 5
    perm_kernel<<<(E + 255) / 256, 256>>>(ei, et, E);            // 6
    const int warps = (E + CHUNK - 1) / CHUNK;
    edge_kernel<<<(warps + 7) / 8, 256>>>(msg, Wt, bt, out, E);  // 7
    final_kernel<<<(N + 7) / 8, 128>>>(We, out, N);              // 8
}

// round 17
// speedup vs baseline: 1.0657x; 1.0011x over previous
#include <cuda_runtime.h>
#include <math.h>

#define D    128
#define HC   128
#define TD   32
#define MD   64
#define AD   96    // TD + MD
#define NMAX 50048
#define EMAX 500224
#define CHUNK 16   // sorted positions per warp

// scratch (static device memory — no allocations allowed)
__device__ float g_q[NMAX * HC];
__device__ float g_k[NMAX * HC];
__device__ float g_v[NMAX * HC];
__device__ float g_sk[NMAX * HC];
__device__ float g_mq[NMAX * 2 * AD];    // per-head We^T q
__device__ float g_accA[NMAX * 2 * AD];  // sum_e w_h * attr
__device__ float g_den[NMAX * 2];
__device__ int   g_cnt[NMAX];
__device__ int   g_cur[NMAX];
__device__ int4  g_es[EMAX];             // sorted (src, dst, time, eid)
__device__ int   g_bsum[64];

typedef unsigned long long ull;

__device__ __forceinline__ ull pack2(float lo, float hi) {
    ull r; asm("mov.b64 %0, {%1, %2};" : "=l"(r) : "f"(lo), "f"(hi)); return r;
}
__device__ __forceinline__ void unpack2(ull v, float& lo, float& hi) {
    asm("mov.b64 {%0, %1}, %2;" : "=f"(lo), "=f"(hi) : "l"(v));
}
__device__ __forceinline__ ull ffma2(ull a, ull b, ull c) {
    ull d; asm("fma.rn.f32x2 %0, %1, %2, %3;" : "=l"(d) : "l"(a), "l"(b), "l"(c)); return d;
}
__device__ __forceinline__ void red_add_v4(float* addr, float4 v) {
    asm volatile("red.global.add.v4.f32 [%0], {%1,%2,%3,%4};"
                 :: "l"(addr), "f"(v.x), "f"(v.y), "f"(v.z), "f"(v.w) : "memory");
}

// ---------------------------------------------------------------------------
// K0: zero accA + cnt
// ---------------------------------------------------------------------------
__global__ void zero_kernel(int n) {
    int i = blockIdx.x * blockDim.x + threadIdx.x;
    if (i < n * 2 * AD) g_accA[i] = 0.0f;
    if (i < n)          g_cnt[i] = 0;
}

// ---------------------------------------------------------------------------
// K1: fused node projections  q/k/v/skip = x @ W + b   (+ zero out/den)
// Weights staged as float4 {wq,wk,wv,ws} per column -> 1 LDS.128 per kk;
// x broadcasts read as LDS.128 (2 row-pairs per load). 5 LDS per kk vs 12.
// ---------------------------------------------------------------------------
__global__ __launch_bounds__(128) void proj_kernel(
    const float* __restrict__ x,
    const float* __restrict__ Wq, const float* __restrict__ bq,
    const float* __restrict__ Wk, const float* __restrict__ bk,
    const float* __restrict__ Wv, const float* __restrict__ bv,
    const float* __restrict__ Ws, const float* __restrict__ bs,
    float* __restrict__ out, int n)
{
    __shared__ __align__(16) float2 xs2[D][10];     // pad 10 -> 16B-aligned rows
    __shared__ __align__(16) float4 W4_s[2][8][HC]; // [buf][kk][c] = {q,k,v,s}
    const int r0 = blockIdx.x * 16;
    const int c  = threadIdx.x;

    #pragma unroll
    for (int r = 0; r < 16; r++) {
        const int row = r0 + r;
        if (row < n) {
            out[(size_t)row * HC + c] = 0.0f;
            if (c < 2) g_den[row * 2 + c] = 0.0f;
        }
    }
    #pragma unroll
    for (int r = 0; r < 16; r++) {
        const int row = r0 + r;
        const float v = (row < n) ? x[(size_t)row * D + c] : 0.0f;
        ((float*)&xs2[c][r >> 1])[r & 1] = v;
    }

    auto stage = [&](int t, int b) {
        const int k0 = t * 8;
        #pragma unroll
        for (int kk = 0; kk < 8; kk++) {
            W4_s[b][kk][c] = make_float4(Wq[(k0 + kk) * HC + c],
                                         Wk[(k0 + kk) * HC + c],
                                         Wv[(k0 + kk) * HC + c],
                                         Ws[(k0 + kk) * HC + c]);
        }
    };

    stage(0, 0);
    __syncthreads();

    ull aq[8], ak[8], av[8], aw[8];
    #pragma unroll
    for (int r = 0; r < 8; r++) { aq[r] = 0; ak[r] = 0; av[r] = 0; aw[r] = 0; }

    for (int t = 0; t < 16; t++) {
        const int b = t & 1;
        if (t + 1 < 16) stage(t + 1, b ^ 1);
        #pragma unroll
        for (int kk = 0; kk < 8; kk++) {
            const int k = t * 8 + kk;
            const float4 w4 = W4_s[b][kk][c];        // LDS.128
            const ull wq2 = pack2(w4.x, w4.x);
            const ull wk2 = pack2(w4.y, w4.y);
            const ull wv2 = pack2(w4.z, w4.z);
            const ull ws2 = pack2(w4.w, w4.w);
            #pragma unroll
            for (int rr = 0; rr < 4; rr++) {
                const ulonglong2 xv = *(const ulonglong2*)&xs2[k][2 * rr]; // LDS.128 bcast
                aq[2 * rr]     = ffma2(xv.x, wq2, aq[2 * rr]);
                aq[2 * rr + 1] = ffma2(xv.y, wq2, aq[2 * rr + 1]);
                ak[2 * rr]     = ffma2(xv.x, wk2, ak[2 * rr]);
                ak[2 * rr + 1] = ffma2(xv.y, wk2, ak[2 * rr + 1]);
                av[2 * rr]     = ffma2(xv.x, wv2, av[2 * rr]);
                av[2 * rr + 1] = ffma2(xv.y, wv2, av[2 * rr + 1]);
                aw[2 * rr]     = ffma2(xv.x, ws2, aw[2 * rr]);
                aw[2 * rr + 1] = ffma2(xv.y, ws2, aw[2 * rr + 1]);
            }
        }
        __syncthreads();
    }

    const float bqv = bq[c], bkv = bk[c], bvv = bv[c], bsv = bs[c];
    #pragma unroll
    for (int r = 0; r < 8; r++) {
        float lo, hi;
        const int rowL = r0 + 2 * r, rowH = rowL + 1;
        unpack2(aq[r], lo, hi);
        if (rowL < n) g_q[(size_t)rowL * HC + c] = lo + bqv;
        if (rowH < n) g_q[(size_t)rowH * HC + c] = hi + bqv;
        unpack2(ak[r], lo, hi);
        if (rowL < n) g_k[(size_t)rowL * HC + c] = lo + bkv;
        if (rowH < n) g_k[(size_t)rowH * HC + c] = hi + bkv;
        unpack2(av[r], lo, hi);
        if (rowL < n) g_v[(size_t)rowL * HC + c] = lo + bvv;
        if (rowH < n) g_v[(size_t)rowH * HC + c] = hi + bvv;
        unpack2(aw[r], lo, hi);
        if (rowL < n) g_sk[(size_t)rowL * HC + c] = lo + bsv;
        if (rowH < n) g_sk[(size_t)rowH * HC + c] = hi + bsv;
    }
}

// ---------------------------------------------------------------------------
// K3: histogram of dst
// ---------------------------------------------------------------------------
__global__ void hist_kernel(const int* __restrict__ ei, int E) {
    int e = blockIdx.x * blockDim.x + threadIdx.x;
    if (e < E) atomicAdd(&g_cnt[ei[E + e]], 1);
}

// ---------------------------------------------------------------------------
// K2: mq[n, h, j] = sum_{c<64} We[j, 64h+c] * q[n, 64h+c]
// ---------------------------------------------------------------------------
__global__ __launch_bounds__(192) void mq_kernel(const float* __restrict__ We, int n) {
    __shared__ float We_s[2][96][65];
    __shared__ __align__(16) float qs[32][128];
    const int r0  = blockIdx.x * 32;
    const int tid = threadIdx.x;
    const int h   = tid / 96, j = tid % 96;

    for (int i = tid; i < 96 * 128; i += 192) {
        const int jj = i >> 7, cc = i & 127;
        We_s[cc >> 6][jj][cc & 63] = We[jj * HC + cc];
    }
    for (int i = tid; i < 32 * 128; i += 192) {
        const int r = i >> 7, c = i & 127, row = r0 + r;
        qs[r][c] = (row < n) ? g_q[(size_t)row * HC + c] : 0.0f;
    }
    __syncthreads();

    ull wr2[32];
    #pragma unroll
    for (int i = 0; i < 32; i++)
        wr2[i] = pack2(We_s[h][j][2 * i], We_s[h][j][2 * i + 1]);

    #pragma unroll
    for (int pass = 0; pass < 2; pass++) {
        ull acc2[16];
        #pragma unroll
        for (int r = 0; r < 16; r++) acc2[r] = 0;
        #pragma unroll 2
        for (int i = 0; i < 16; i++) {
            const ull w2a = wr2[2 * i], w2b = wr2[2 * i + 1];
            #pragma unroll
            for (int r = 0; r < 16; r++) {
                const ulonglong2 q4 =
                    *(const ulonglong2*)&qs[pass * 16 + r][64 * h + 4 * i];
                acc2[r] = ffma2(q4.x, w2a, acc2[r]);
                acc2[r] = ffma2(q4.y, w2b, acc2[r]);
            }
        }
        #pragma unroll
        for (int r = 0; r < 16; r++) {
            float lo, hi; unpack2(acc2[r], lo, hi);
            const int row = r0 + pass * 16 + r;
            if (row < n) g_mq[(size_t)row * (2 * AD) + h * AD + j] = lo + hi;
        }
    }
}

// ---------------------------------------------------------------------------
// K4a: per-block sums of cnt
// ---------------------------------------------------------------------------
__global__ __launch_bounds__(1024) void scan_bsum_kernel(int n) {
    __shared__ int ws[32];
    const int i = blockIdx.x * 1024 + threadIdx.x;
    int v = (i < n) ? g_cnt[i] : 0;
    #pragma unroll
    for (int off = 16; off; off >>= 1) v += __shfl_xor_sync(~0u, v, off);
    if ((threadIdx.x & 31) == 0) ws[threadIdx.x >> 5] = v;
    __syncthreads();
    if (threadIdx.x < 32) {
        int s = ws[threadIdx.x];
        #pragma unroll
        for (int off = 16; off; off >>= 1) s += __shfl_xor_sync(~0u, s, off);
        if (threadIdx.x == 0) g_bsum[blockIdx.x] = s;
    }
}
// K4b: apply (each block sums preceding block sums itself)
__global__ __launch_bounds__(1024) void scan_apply_kernel(int n) {
    __shared__ int s[1024];
    const int tid = threadIdx.x;
    const int i = blockIdx.x * 1024 + tid;
    int base = 0;
    for (int b = 0; b < blockIdx.x; b++) base += g_bsum[b];
    const int v = (i < n) ? g_cnt[i] : 0;
    s[tid] = v;
    __syncthreads();
    #pragma unroll
    for (int off = 1; off < 1024; off <<= 1) {
        const int o = (tid >= off) ? s[tid - off] : 0;
        __syncthreads();
        s[tid] += o;
        __syncthreads();
    }
    if (i < n) g_cur[i] = base + s[tid] - v;
}

// ---------------------------------------------------------------------------
// K5: build sorted edge records (src, dst, time, eid)
// ---------------------------------------------------------------------------
__global__ void perm_kernel(const int* __restrict__ ei, const int* __restrict__ et, int E) {
    int e = blockIdx.x * blockDim.x + threadIdx.x;
    if (e < E) {
        const int s = ei[e], d = ei[E + e], t = et[e];
        const int pos = atomicAdd(&g_cur[d], 1);
        g_es[pos] = make_int4(s, d, t, e);
    }
}

// ---------------------------------------------------------------------------
// K6: edge kernel over dst-sorted records, 2 edges per iteration (R11 layout).
// ---------------------------------------------------------------------------
__global__ __launch_bounds__(256) void edge_kernel(
    const float* __restrict__ msg,  // [E,64]
    const float* __restrict__ Wt, const float* __restrict__ bt,
    float* __restrict__ out, int E)
{
    const int gw   = (blockIdx.x * blockDim.x + threadIdx.x) >> 5;
    const int lane = threadIdx.x & 31;
    int p = gw * CHUNK;
    if (p >= E) return;
    const int pend = min(p + CHUNK, E);

    const int  ll      = lane % 12;
    const bool is_a    = lane < 24;
    const bool a_head1 = (lane >= 12) && (lane < 24);
    const bool is_cos  = is_a && (ll < 4);

    float wt8[8], bt8[8];
    if (is_cos) {
        #pragma unroll
        for (int m = 0; m < 8; m++) { wt8[m] = Wt[8 * ll + m]; bt8[m] = bt[8 * ll + m]; }
    }

    int cur_dst = -1;
    float4 acc_v = make_float4(0, 0, 0, 0);
    float  accA[8] = {};
    float  den0 = 0.0f, den1 = 0.0f;

    auto flush = [&]() {
        if (cur_dst >= 0) {
            red_add_v4(out + (size_t)cur_dst * HC + 4 * lane, acc_v);
            if (is_a) {
                float* a = g_accA + (size_t)cur_dst * (2 * AD) + 8 * lane;
                red_add_v4(a,     make_float4(accA[0], accA[1], accA[2], accA[3]));
                red_add_v4(a + 4, make_float4(accA[4], accA[5], accA[6], accA[7]));
            }
            if (lane == 0)  atomicAdd(&g_den[cur_dst * 2],     den0);
            if (lane == 16) atomicAdd(&g_den[cur_dst * 2 + 1], den1);
            acc_v = make_float4(0, 0, 0, 0);
            #pragma unroll
            for (int m = 0; m < 8; m++) accA[m] = 0.0f;
            den0 = 0.0f; den1 = 0.0f;
        }
    };

    for (int pb = p; pb < pend; pb += 2) {
        const bool has1 = (pb + 1 < pend);
        const int4 m0 = g_es[pb];
        const int4 m1 = has1 ? g_es[pb + 1] : m0;
        const int s0 = m0.x, dA = m0.y, t0 = m0.z, e0 = m0.w;
        const int s1 = m1.x, dB = m1.y, t1 = m1.z, e1 = m1.w;

        // ---- issue all gathers up front (MLP) ----
        const float4 k40 = ((const float4*)(g_k + (size_t)s0 * HC))[lane];
        const float4 k41 = ((const float4*)(g_k + (size_t)s1 * HC))[lane];
        const float4 v40 = ((const float4*)(g_v + (size_t)s0 * HC))[lane];
        const float4 v41 = ((const float4*)(g_v + (size_t)s1 * HC))[lane];
        const float4 q40 = ((const float4*)(g_q + (size_t)dA * HC))[lane];
        const float4 q41 = ((const float4*)(g_q + (size_t)dB * HC))[lane];

        float mq0[8] = {}, mq1[8] = {};
        if (is_a) {
            const float4 a0 = *(const float4*)(g_mq + (size_t)dA * (2 * AD) + 8 * lane);
            const float4 b0 = *(const float4*)(g_mq + (size_t)dA * (2 * AD) + 8 * lane + 4);
            const float4 a1 = *(const float4*)(g_mq + (size_t)dB * (2 * AD) + 8 * lane);
            const float4 b1 = *(const float4*)(g_mq + (size_t)dB * (2 * AD) + 8 * lane + 4);
            mq0[0]=a0.x; mq0[1]=a0.y; mq0[2]=a0.z; mq0[3]=a0.w;
            mq0[4]=b0.x; mq0[5]=b0.y; mq0[6]=b0.z; mq0[7]=b0.w;
            mq1[0]=a1.x; mq1[1]=a1.y; mq1[2]=a1.z; mq1[3]=a1.w;
            mq1[4]=b1.x; mq1[5]=b1.y; mq1[6]=b1.z; mq1[7]=b1.w;
        }

        // ---- attr slices ----
        float a80[8] = {}, a81[8] = {};
        if (is_cos) {
            const float tf0 = (float)t0, tf1 = (float)t1;
            #pragma unroll
            for (int m = 0; m < 8; m++) {
                a80[m] = cosf(tf0 * wt8[m] + bt8[m]);
                a81[m] = cosf(tf1 * wt8[m] + bt8[m]);
            }
        } else if (is_a) {
            const float4 x00 = *(const float4*)(msg + (size_t)e0 * MD + 8 * (ll - 4));
            const float4 x01 = *(const float4*)(msg + (size_t)e0 * MD + 8 * (ll - 4) + 4);
            const float4 x10 = *(const float4*)(msg + (size_t)e1 * MD + 8 * (ll - 4));
            const float4 x11 = *(const float4*)(msg + (size_t)e1 * MD + 8 * (ll - 4) + 4);
            a80[0]=x00.x; a80[1]=x00.y; a80[2]=x00.z; a80[3]=x00.w;
            a80[4]=x01.x; a80[5]=x01.y; a80[6]=x01.z; a80[7]=x01.w;
            a81[0]=x10.x; a81[1]=x10.y; a81[2]=x10.z; a81[3]=x10.w;
            a81[4]=x11.x; a81[5]=x11.y; a81[6]=x11.z; a81[7]=x11.w;
        }

        // ---- alpha partials (4 interleaved reduce chains) ----
        const float qk0 = q40.x*k40.x + q40.y*k40.y + q40.z*k40.z + q40.w*k40.w;
        const float qk1 = q41.x*k41.x + q41.y*k41.y + q41.z*k41.z + q41.w*k41.w;
        float am0 = 0.0f, am1 = 0.0f;
        #pragma unroll
        for (int m = 0; m < 8; m++) { am0 += a80[m]*mq0[m]; am1 += a81[m]*mq1[m]; }

        float p00 = (lane < 16 ? qk0 : 0.0f) + ((is_a && !a_head1) ? am0 : 0.0f);
        float p01 = (lane >= 16 ? qk0 : 0.0f) + (a_head1 ? am0 : 0.0f);
        float p10 = (lane < 16 ? qk1 : 0.0f) + ((is_a && !a_head1) ? am1 : 0.0f);
        float p11 = (lane >= 16 ? qk1 : 0.0f) + (a_head1 ? am1 : 0.0f);
        #pragma unroll
        for (int off = 16; off; off >>= 1) {
            p00 += __shfl_xor_sync(~0u, p00, off);
            p01 += __shfl_xor_sync(~0u, p01, off);
            p10 += __shfl_xor_sync(~0u, p10, off);
            p11 += __shfl_xor_sync(~0u, p11, off);
        }
        const float w00 = __expf(0.125f * p00);
        const float w01 = __expf(0.125f * p01);
        const float w10 = __expf(0.125f * p10);
        const float w11 = __expf(0.125f * p11);

        // ---- accumulate edge 0 ----
        if (dA != cur_dst) { flush(); cur_dst = dA; }
        {
            const float wv = (lane < 16) ? w00 : w01;
            acc_v.x += wv * v40.x; acc_v.y += wv * v40.y;
            acc_v.z += wv * v40.z; acc_v.w += wv * v40.w;
            const float wa = a_head1 ? w01 : w00;
            #pragma unroll
            for (int m = 0; m < 8; m++) accA[m] += wa * a80[m];
            den0 += w00; den1 += w01;
        }
        // ---- accumulate edge 1 ----
        if (has1) {
            if (dB != cur_dst) { flush(); cur_dst = dB; }
            const float wv = (lane < 16) ? w10 : w11;
            acc_v.x += wv * v41.x; acc_v.y += wv * v41.y;
            acc_v.z += wv * v41.z; acc_v.w += wv * v41.w;
            const float wa = a_head1 ? w11 : w10;
            #pragma unroll
            for (int m = 0; m < 8; m++) accA[m] += wa * a81[m];
            den0 += w10; den1 += w11;
        }
    }
    flush();
}

// ---------------------------------------------------------------------------
// K7: out = (out_v + accA @ We_head) / den + skip   (8 rows per block)
// ---------------------------------------------------------------------------
__global__ __launch_bounds__(128) void final_kernel(
    const float* __restrict__ We, float* __restrict__ out, int n)
{
    __shared__ __align__(16) float aS[8][2 * AD];
    const int r0 = blockIdx.x * 8;
    const int c  = threadIdx.x;
    const int h  = c >> 6;

    for (int i = c; i < 8 * 2 * AD; i += 128) {
        const int r = i / (2 * AD), jj = i % (2 * AD), row = r0 + r;
        aS[r][jj] = (row < n) ? g_accA[(size_t)row * (2 * AD) + jj] : 0.0f;
    }
    __syncthreads();

    float acc[8] = {};
    #pragma unroll 4
    for (int j = 0; j < AD; j++) {
        const float wv = We[j * HC + c];
        #pragma unroll
        for (int r = 0; r < 8; r++) acc[r] += wv * aS[r][AD * h + j];
    }
    #pragma unroll
    for (int r = 0; r < 8; r++) {
        const int row = r0 + r;
        if (row < n) {
            const size_t o = (size_t)row * HC + c;
            const float den = g_den[row * 2 + h] + 1e-16f;
            out[o] = (out[o] + acc[r]) / den + g_sk[o];
        }
    }
}

// ---------------------------------------------------------------------------
extern "C" void kernel_launch(void* const* d_in, const int* in_sizes, int n_in,
                              void* d_out, int out_size)
{
    const float* x   = (const float*)d_in[0];
    const int*   ei  = (const int*)d_in[1];
    const int*   et  = (const int*)d_in[2];
    const float* msg = (const float*)d_in[3];
    const float* Wt  = (const float*)d_in[4];
    const float* bt  = (const float*)d_in[5];
    const float* Wq  = (const float*)d_in[6];
    const float* bq  = (const float*)d_in[7];
    const float* Wk  = (const float*)d_in[8];
    const float* bk  = (const float*)d_in[9];
    const float* Wv  = (const float*)d_in[10];
    const float* bv  = (const float*)d_in[11];
    const float* We  = (const float*)d_in[12];
    const float* Ws  = (const float*)d_in[13];
    const float* bs  = (const float*)d_in[14];
    float* out = (float*)d_out;

    const int N = in_sizes[0] / D;
    const int E = in_sizes[2];
    const int NB = (N + 1023) / 1024;

    zero_kernel<<<(N * 2 * AD + 255) / 256, 256>>>(N);           // 0
    hist_kernel<<<(E + 255) / 256, 256>>>(ei, E);                // 1
    scan_bsum_kernel<<<NB, 1024>>>(N);                           // 2
    proj_kernel<<<(N + 15) / 16, 128>>>(x, Wq, bq, Wk, bk,       // 3 <- capture slot
                                        Wv, bv, Ws, bs, out, N);
    mq_kernel<<<(N + 31) / 32, 192>>>(We, N);                    // 4
    scan_apply_kernel<<<NB, 1024>>>(N);                          // 5
    perm_kernel<<<(E + 255) / 256, 256>>>(ei, et, E);            // 6
    const int warps = (E + CHUNK - 1) / CHUNK;
    edge_kernel<<<(warps + 7) / 8, 256>>>(msg, Wt, bt, out, E);  // 7
    final_kernel<<<(N + 7) / 8, 128>>>(We, out, N);              // 8
}